// round 15
// baseline (speedup 1.0000x reference)
#include <cuda_runtime.h>

// LocalVariation: out[b, k, y, x] = x[b,y,x] - xp[b, y+i, x+j]  (replicate pad, 5x5, skip center)
// Input : [16, 1, 512, 512] f32
// Output: [16, 24, 512, 512] f32
//
// Persistent kernel: 592 CTAs (4/SM x 148), each loops over ~7 tiles of the
// R14 geometry (256x4 px, blockDim (128,4)=512 thr, 2 px/thread, float2 __stcs).
// Next tile's input is prefetched into the alternate smem buffer via cp.async
// while the current tile computes/stores -> fill latency hidden, no wave gaps.

#define KSZ   5
#define PAD   2
#define H     512
#define W     512
#define B     16
#define NCH   24
#define TILE_X 256
#define TILE_Y 4
#define NTX   (W / TILE_X)               // 2
#define NTY   (H / TILE_Y)               // 128
#define NTILES (NTX * NTY * B)           // 4096
#define NCTAS 592                        // 148 SMs x 4 resident
#define SM_W  (TILE_X + 2 * PAD)         // 260
#define SM_STRIDE 264
#define SM_H  (TILE_Y + 2 * PAD)         // 8
#define SM_ELEMS (SM_H * SM_W)           // 2080

__device__ __forceinline__ void cp_async4(float* dst_smem, const float* src) {
    unsigned sa = (unsigned)__cvta_generic_to_shared(dst_smem);
    asm volatile("cp.async.ca.shared.global [%0], [%1], 4;" :: "r"(sa), "l"(src));
}

__device__ __forceinline__ void fill_tile(float* __restrict__ buf, int t, int tid,
                                          const float* __restrict__ in) {
    const int bxt = t & (NTX - 1);
    const int byt = (t >> 1) & (NTY - 1);
    const int b   = t >> 8;                    // t / (NTX*NTY)
    const int by0 = byt * TILE_Y;
    const int bx0 = bxt * TILE_X;
    const float* inb = in + b * (H * W);
    #pragma unroll
    for (int it = 0; it < 5; it++) {
        int idx = tid + it * 512;
        if (idx < SM_ELEMS) {
            int r = idx / SM_W;
            int c = idx - r * SM_W;
            int gy = by0 + r - PAD;
            int gx = bx0 + c - PAD;
            gy = gy < 0 ? 0 : (gy > H - 1 ? H - 1 : gy);
            gx = gx < 0 ? 0 : (gx > W - 1 ? W - 1 : gx);
            cp_async4(&buf[r * SM_STRIDE + c], &inb[gy * W + gx]);
        }
    }
}

__device__ __forceinline__ void compute_tile(const float* __restrict__ sm, int t,
                                             int tx, int ty,
                                             float* __restrict__ out) {
    const int bxt = t & (NTX - 1);
    const int byt = (t >> 1) & (NTY - 1);
    const int b   = t >> 8;
    const int by0 = byt * TILE_Y;
    const int bx0 = bxt * TILE_X;
    const int px  = tx * 2;

    const float2 cC = *(const float2*)&sm[(ty + PAD) * SM_STRIDE + px + 2];
    const float c0 = cC.x, c1 = cC.y;

    const int gy = by0 + ty;
    float* outp = out + ((long long)b * NCH * H + gy) * W + bx0 + px;

    int k = 0;
    #pragma unroll
    for (int i = 0; i < KSZ; i++) {
        const float* rowp = &sm[(ty + i) * SM_STRIDE + px];
        float2 a = *(const float2*)(rowp + 0);
        float2 d = *(const float2*)(rowp + 2);
        float2 e = *(const float2*)(rowp + 4);
        float rr[6] = {a.x, a.y, d.x, d.y, e.x, e.y};

        #pragma unroll
        for (int j = 0; j < KSZ; j++) {
            if (i == PAD && j == PAD) continue;
            float2 v;
            v.x = c0 - rr[j + 0];
            v.y = c1 - rr[j + 1];
            __stcs((float2*)(outp + (long long)k * (H * W)), v);
            k++;
        }
    }
}

__global__ __launch_bounds__(512, 4)
void localvar_kernel(const float* __restrict__ in, float* __restrict__ out) {
    __shared__ float sm[2][SM_H * SM_STRIDE];   // 2 x 8448 B

    const int tid = threadIdx.y * 128 + threadIdx.x;
    const int tx  = threadIdx.x;
    const int ty  = threadIdx.y;

    int t = blockIdx.x;                 // first tile for this CTA (< NCTAS <= NTILES)
    int cur = 0;

    fill_tile(sm[0], t, tid, in);
    asm volatile("cp.async.commit_group;" ::: "memory");

    while (t < NTILES) {
        int tn = t + NCTAS;
        if (tn < NTILES) {
            // Prefetch next tile into the other buffer (its last reader finished
            // at the previous iteration's trailing __syncthreads).
            fill_tile(sm[cur ^ 1], tn, tid, in);
            asm volatile("cp.async.commit_group;" ::: "memory");
            asm volatile("cp.async.wait_group 1;" ::: "memory");   // current fill done
        } else {
            asm volatile("cp.async.wait_group 0;" ::: "memory");   // drain everything
        }
        __syncthreads();

        compute_tile(sm[cur], t, tx, ty, out);

        __syncthreads();     // all readers of sm[cur] done before it is refilled
        cur ^= 1;
        t = tn;
    }
}

extern "C" void kernel_launch(void* const* d_in, const int* in_sizes, int n_in,
                              void* d_out, int out_size) {
    const float* x = (const float*)d_in[0];
    float* out = (float*)d_out;
    dim3 block(128, 4, 1);
    dim3 grid(NCTAS, 1, 1);
    localvar_kernel<<<grid, block>>>(x, out);
}

// round 17
// speedup vs baseline: 1.0255x; 1.0255x over previous
#include <cuda_runtime.h>

// LocalVariation: out[b, k, y, x] = x[b,y,x] - xp[b, y+i, x+j]  (replicate pad, 5x5, skip center)
// Input : [16, 1, 512, 512] f32
// Output: [16, 24, 512, 512] f32
//
// R14 geometry (best: 61.5us): tile 256x4, blockDim (128,4)=512 thr, 2 px/thread,
// 4096 blocks -> 7 waves at 98.9% utilization.
// Single-variable change vs R14: plain float2 stores instead of __stcs, to test
// whether default L2 write-back aggregation beats evict-first streaming.

#define KSZ   5
#define PAD   2
#define H     512
#define W     512
#define B     16
#define NCH   24
#define TILE_X 256
#define TILE_Y 4
#define NTX   (W / TILE_X)         // 2 x-tiles
#define SM_W  (TILE_X + 2 * PAD)   // 260 valid cols
#define SM_STRIDE 264              // row stride
#define SM_H  (TILE_Y + 2 * PAD)   // 8 rows
#define SM_ELEMS (SM_H * SM_W)     // 2080

__global__ __launch_bounds__(512, 4)
void localvar_kernel(const float* __restrict__ in, float* __restrict__ out) {
    __shared__ float sm[SM_H * SM_STRIDE];   // 8448 B

    const int bxt = blockIdx.x & (NTX - 1);        // x-tile 0..1
    const int byt = blockIdx.x >> 1;               // y-tile 0..127
    const int b   = blockIdx.y;
    const int by0 = byt * TILE_Y;
    const int bx0 = bxt * TILE_X;

    const int tid = threadIdx.y * 128 + threadIdx.x;
    const float* inb = in + b * (H * W);

    // ---- fill smem tile with replicate-clamped input ----
    #pragma unroll
    for (int it = 0; it < 5; it++) {
        int idx = tid + it * 512;
        if (idx < SM_ELEMS) {
            int r = idx / SM_W;
            int c = idx - r * SM_W;
            int gy = by0 + r - PAD;
            int gx = bx0 + c - PAD;
            gy = gy < 0 ? 0 : (gy > H - 1 ? H - 1 : gy);
            gx = gx < 0 ? 0 : (gx > W - 1 ? W - 1 : gx);
            sm[r * SM_STRIDE + c] = inb[gy * W + gx];
        }
    }
    __syncthreads();

    // ---- compute: 2 consecutive x pixels per thread ----
    const int tx = threadIdx.x;       // 0..127
    const int ty = threadIdx.y;       // 0..3
    const int px = tx * 2;            // local x of first of 2 pixels (even)

    const float2 cC = *(const float2*)&sm[(ty + PAD) * SM_STRIDE + px + 2];
    const float c0 = cC.x, c1 = cC.y;

    const int gy = by0 + ty;
    float* outp = out + ((long long)b * NCH * H + gy) * W + bx0 + px;

    int k = 0;
    #pragma unroll
    for (int i = 0; i < KSZ; i++) {
        const float* rowp = &sm[(ty + i) * SM_STRIDE + px];
        float2 a = *(const float2*)(rowp + 0);
        float2 d = *(const float2*)(rowp + 2);
        float2 e = *(const float2*)(rowp + 4);
        float rr[6] = {a.x, a.y, d.x, d.y, e.x, e.y};

        #pragma unroll
        for (int j = 0; j < KSZ; j++) {
            if (i == PAD && j == PAD) continue;
            float2 v;
            v.x = c0 - rr[j + 0];
            v.y = c1 - rr[j + 1];
            *(float2*)(outp + (long long)k * (H * W)) = v;   // plain store (was __stcs)
            k++;
        }
    }
}

extern "C" void kernel_launch(void* const* d_in, const int* in_sizes, int n_in,
                              void* d_out, int out_size) {
    const float* x = (const float*)d_in[0];
    float* out = (float*)d_out;
    dim3 block(128, 4, 1);
    dim3 grid(NTX * (H / TILE_Y), B, 1);   // 256 x 16 = 4096 blocks
    localvar_kernel<<<grid, block>>>(x, out);
}